// round 1
// baseline (speedup 1.0000x reference)
#include <cuda_runtime.h>
#include <cstdint>
#include <math.h>

#define T_STEPS 512
#define B_ROWS  64
#define F_DIM   256
#define U_DIM   1024
#define NG      4096
#define NB      128
#define NT      256

// ---------------- persistent device state ----------------
__device__ float g_h[2][3][B_ROWS][U_DIM];   // ping-pong hidden state
__device__ float g_c[2][3][B_ROWS][U_DIM];   // ping-pong cell state
__device__ float g_emit[B_ROWS * F_DIM];     // previous emit
__device__ float g_y[B_ROWS * F_DIM];        // dense output scratch

__device__ unsigned g_bar_count = 0;
__device__ volatile unsigned g_bar_gen = 0;

// ---------------- grid-wide barrier ----------------
__device__ __forceinline__ void grid_barrier() {
    __syncthreads();
    if (threadIdx.x == 0) {
        __threadfence();                         // publish this CTA's writes
        unsigned gen = g_bar_gen;                // read BEFORE arriving
        if (atomicAdd(&g_bar_count, 1u) == (unsigned)(NB - 1)) {
            g_bar_count = 0;
            __threadfence();                     // order reset before gen bump
            g_bar_gen = gen + 1u;
        } else {
            while (g_bar_gen == gen) { }
        }
    }
    __syncthreads();
    __threadfence();                             // acquire: flush stale L1 (CCTL.IVALL)
}

// ---------------- math helpers ----------------
__device__ __forceinline__ float sigf(float x) { return 1.0f / (1.0f + expf(-x)); }

__device__ __forceinline__ void ffma2(unsigned long long& acc,
                                      unsigned long long a,
                                      unsigned long long b) {
    asm("fma.rn.f32x2 %0, %1, %2, %0;" : "+l"(acc) : "l"(a), "l"(b));
}
__device__ __forceinline__ unsigned long long packf2(float lo, float hi) {
    unsigned long long r;
    asm("mov.b64 %0, {%1, %2};" : "=l"(r) : "f"(lo), "f"(hi));
    return r;
}
__device__ __forceinline__ float sumf2(unsigned long long v) {
    float lo = __uint_as_float((unsigned)(v & 0xffffffffu));
    float hi = __uint_as_float((unsigned)(v >> 32));
    return lo + hi;
}

// ---------------- one LSTM layer: z = [A0, Hold] @ W + b, then gates ----------------
// CTA handles u-columns [cta*8, cta*8+8) across all 4 gate blocks (32 cols x 64 rows).
__device__ __forceinline__ void layer_phase(
    const float* __restrict__ A0, int lda0, int Kin,      // input segment
    const float* __restrict__ Hold,                       // [64][1024] hidden segment
    const float* __restrict__ W,                          // [(Kin+1024)][4096]
    const float* __restrict__ bias,                       // [4096]
    const float* __restrict__ Cold,                       // [64][1024]
    float* __restrict__ Cnew, float* __restrict__ Hnew,   // [64][1024]
    float* As, float* zs, int cta, int tid)
{
    const int c32  = tid & 31;
    const int rg   = tid >> 5;
    const int r0   = rg * 8;
    const int gate = c32 >> 3;
    const int uo   = c32 & 7;
    const int u0   = cta * 8;
    const int n    = gate * 1024 + u0 + uo;

    unsigned long long acc64[8];
    #pragma unroll
    for (int i = 0; i < 8; i++) acc64[i] = 0ull;

    #pragma unroll
    for (int seg = 0; seg < 2; seg++) {
        const float* A   = seg ? Hold : A0;
        const int    lda = seg ? U_DIM : lda0;
        const int    Ks  = seg ? U_DIM : Kin;
        const int    wr0 = seg ? Kin : 0;

        for (int kb = 0; kb < Ks; kb += 64) {
            __syncthreads();  // protect previous tile reads
            // load A tile [64][64] into smem (coalesced float4)
            #pragma unroll
            for (int qv = 0; qv < 4; qv++) {
                int idx = tid + qv * NT;       // float4 index 0..1023
                int r   = idx >> 4;            // 16 float4 per row
                int kq  = idx & 15;
                *(float4*)&As[r * 64 + kq * 4] =
                    *(const float4*)&A[(size_t)r * lda + kb + kq * 4];
            }
            __syncthreads();

            const float* Wp = W + (size_t)(wr0 + kb) * NG + n;
            #pragma unroll 4
            for (int k4 = 0; k4 < 64; k4 += 4) {
                float w0 = Wp[(size_t)(k4 + 0) * NG];
                float w1 = Wp[(size_t)(k4 + 1) * NG];
                float w2 = Wp[(size_t)(k4 + 2) * NG];
                float w3 = Wp[(size_t)(k4 + 3) * NG];
                unsigned long long w01 = packf2(w0, w1);
                unsigned long long w23 = packf2(w2, w3);
                #pragma unroll
                for (int i = 0; i < 8; i++) {
                    ulonglong2 a2 = *(const ulonglong2*)&As[(r0 + i) * 64 + k4];
                    ffma2(acc64[i], a2.x, w01);
                    ffma2(acc64[i], a2.y, w23);
                }
            }
        }
    }

    const float bv = bias[n];
    __syncthreads();
    #pragma unroll
    for (int i = 0; i < 8; i++)
        zs[(r0 + i) * 32 + c32] = sumf2(acc64[i]) + bv;
    __syncthreads();

    // fused LSTM cell update: 512 (b,u) pairs per CTA, 2 per thread
    #pragma unroll
    for (int pp = 0; pp < 2; pp++) {
        int pidx = tid + pp * NT;
        int row  = pidx >> 3;
        int uu   = pidx & 7;
        float zi = zs[row * 32 +  0 + uu];
        float zj = zs[row * 32 +  8 + uu];
        float zf = zs[row * 32 + 16 + uu];
        float zo = zs[row * 32 + 24 + uu];
        int   ui = u0 + uu;
        float co = Cold[row * U_DIM + ui];
        float cn = co * sigf(zf + 1.0f) + sigf(zi) * tanhf(zj);
        float hn = sigf(zo) * tanhf(cn);
        Cnew[row * U_DIM + ui] = cn;
        Hnew[row * U_DIM + ui] = hn;
    }
}

// ---------------- dense projection y = h2 @ Wd + bd ----------------
// 128 CTAs tiled as 4 row-blocks (16 rows) x 32 col-blocks (8 cols).
__device__ __forceinline__ void dense_phase(
    const float* __restrict__ H2, const float* __restrict__ Wd,
    const float* __restrict__ bd, float* As, int cta, int tid)
{
    const int rb  = cta >> 5;
    const int cb  = cta & 31;
    const int r   = tid >> 3;   // 0..31 (only <16 used)
    const int cl  = tid & 7;
    const int col = cb * 8 + cl;
    float acc = 0.0f;

    for (int kb = 0; kb < U_DIM; kb += 256) {
        __syncthreads();
        #pragma unroll
        for (int qv = 0; qv < 4; qv++) {
            int idx = tid + qv * NT;       // float4 idx 0..1023
            int rr  = idx >> 6;            // 64 float4 per 256-row
            int kq  = idx & 63;
            *(float4*)&As[rr * 256 + kq * 4] =
                *(const float4*)&H2[(size_t)(rb * 16 + rr) * U_DIM + kb + kq * 4];
        }
        __syncthreads();
        if (tid < 128) {
            #pragma unroll 8
            for (int k = 0; k < 256; k++)
                acc = fmaf(As[r * 256 + k], Wd[(size_t)(kb + k) * F_DIM + col], acc);
        }
    }
    if (tid < 128)
        g_y[(rb * 16 + r) * F_DIM + col] = acc + bd[col];
}

// ---------------- layernorm + relu + emit ----------------
__device__ __forceinline__ void ln_phase(
    const float* __restrict__ gamma, const float* __restrict__ beta,
    float* __restrict__ out, float* red, int t, int cta, int tid)
{
    if (cta >= B_ROWS) return;  // idle CTAs go straight to grid barrier
    const int row = cta;
    float v = g_y[row * F_DIM + tid];

    red[tid] = v; __syncthreads();
    #pragma unroll
    for (int s = 128; s > 0; s >>= 1) {
        if (tid < s) red[tid] += red[tid + s];
        __syncthreads();
    }
    float mu = red[0] * (1.0f / 256.0f);
    __syncthreads();

    float d = v - mu;
    red[tid] = d * d; __syncthreads();
    #pragma unroll
    for (int s = 128; s > 0; s >>= 1) {
        if (tid < s) red[tid] += red[tid + s];
        __syncthreads();
    }
    float var = red[0] * (1.0f / 256.0f);

    float o = d * rsqrtf(var + 1e-12f) * gamma[tid] + beta[tid];
    o = fmaxf(o, 0.0f);
    g_emit[row * F_DIM + tid] = o;
    out[(size_t)row * T_STEPS * F_DIM + (size_t)t * F_DIM + tid] = o;
}

// ---------------- persistent kernel ----------------
__global__ void __launch_bounds__(NT, 1) lstm_persistent(
    const float* __restrict__ input, const unsigned char* __restrict__ condb,
    const float* __restrict__ W0, const float* __restrict__ b0,
    const float* __restrict__ W1, const float* __restrict__ b1,
    const float* __restrict__ W2, const float* __restrict__ b2,
    const float* __restrict__ Wd, const float* __restrict__ bd,
    const float* __restrict__ gamma, const float* __restrict__ beta,
    float* __restrict__ out)
{
    __shared__ __align__(16) float As[64 * 64];   // A tiles / dense h tiles
    __shared__ float zs[64 * 32];                 // gate pre-activations
    __shared__ float red[NT];                     // LN reductions

    const int cta = blockIdx.x, tid = threadIdx.x;

    // --- detect dtype of conditioned_lst: bool-u8 vs int32 vs float32 ---
    int p1 = 0, p23 = 0;
    for (int i = tid; i < T_STEPS; i += NT) {
        unsigned char bv = condb[i];
        if (bv != 0) {
            if ((i & 3) == 1) p1 = 1;
            if ((i & 3) >= 2) p23 = 1;
        }
    }
    const int is_u8  = __syncthreads_or(p1);
    const int is_f32 = __syncthreads_or(p23) && !is_u8;
    const int*   cond32 = (const int*)condb;
    const float* condf  = (const float*)condb;

    // --- zero init both ping-pong state buffers ---
    {
        float* hflat = &g_h[0][0][0][0];
        float* cflat = &g_c[0][0][0][0];
        const int tot = 2 * 3 * B_ROWS * U_DIM;
        for (int i = cta * NT + tid; i < tot; i += NB * NT) {
            hflat[i] = 0.0f; cflat[i] = 0.0f;
        }
    }
    grid_barrier();

    for (int t = 0; t < T_STEPS; t++) {
        const int p = t & 1, q = p ^ 1;
        int cv;
        if (is_u8)       cv = (int)condb[t];
        else if (is_f32) cv = (condf[t] != 0.0f);
        else             cv = cond32[t];
        const bool  use_in = (t == 0) || (cv != 0);
        const float* x  = use_in ? (input + (size_t)t * F_DIM) : g_emit;
        const int   ldx = use_in ? (T_STEPS * F_DIM) : F_DIM;

        layer_phase(x, ldx, F_DIM, &g_h[q][0][0][0], W0, b0,
                    &g_c[q][0][0][0], &g_c[p][0][0][0], &g_h[p][0][0][0],
                    As, zs, cta, tid);
        grid_barrier();

        layer_phase(&g_h[p][0][0][0], U_DIM, U_DIM, &g_h[q][1][0][0], W1, b1,
                    &g_c[q][1][0][0], &g_c[p][1][0][0], &g_h[p][1][0][0],
                    As, zs, cta, tid);
        grid_barrier();

        layer_phase(&g_h[p][1][0][0], U_DIM, U_DIM, &g_h[q][2][0][0], W2, b2,
                    &g_c[q][2][0][0], &g_c[p][2][0][0], &g_h[p][2][0][0],
                    As, zs, cta, tid);
        grid_barrier();

        dense_phase(&g_h[p][2][0][0], Wd, bd, As, cta, tid);
        grid_barrier();

        ln_phase(gamma, beta, out, red, t, cta, tid);
        grid_barrier();
    }
}

extern "C" void kernel_launch(void* const* d_in, const int* in_sizes, int n_in,
                              void* d_out, int out_size) {
    (void)in_sizes; (void)n_in; (void)out_size;
    lstm_persistent<<<NB, NT>>>(
        (const float*)d_in[0], (const unsigned char*)d_in[1],
        (const float*)d_in[2], (const float*)d_in[3],
        (const float*)d_in[4], (const float*)d_in[5],
        (const float*)d_in[6], (const float*)d_in[7],
        (const float*)d_in[8], (const float*)d_in[9],
        (const float*)d_in[10], (const float*)d_in[11],
        (float*)d_out);
}

// round 2
// speedup vs baseline: 1.5420x; 1.5420x over previous
#include <cuda_runtime.h>
#include <cstdint>
#include <math.h>

#define T_STEPS 512
#define B_ROWS  64
#define F_DIM   256
#define U_DIM   1024
#define NG      4096
#define NB      128
#define NT      256
#define KT      128   // k-tile size

// ---------------- persistent device state ----------------
__device__ float g_Wr[(1280 + 2048 + 2048) * 4096];  // gate-interleaved weights
__device__ float g_h[2][3][B_ROWS][U_DIM];
__device__ float g_c[2][3][B_ROWS][U_DIM];
__device__ float g_emit[B_ROWS * F_DIM];

__device__ unsigned g_bar_count = 0;
__device__ volatile unsigned g_bar_gen = 0;

// ---------------- weight reorder: Wr[k][u*4+g] = W[k][g*1024+u] ----------------
__global__ void reorder_w(const float* __restrict__ W, float* __restrict__ Wr, int total) {
    int idx = blockIdx.x * blockDim.x + threadIdx.x;
    if (idx >= total) return;
    int k = idx >> 12;
    int n = idx & 4095;
    int g = n >> 10, u = n & 1023;
    Wr[((size_t)k << 12) + (u << 2) + g] = W[idx];
}

// ---------------- grid-wide barrier ----------------
__device__ __forceinline__ void grid_barrier() {
    __syncthreads();
    if (threadIdx.x == 0) {
        __threadfence();
        unsigned gen = g_bar_gen;
        if (atomicAdd(&g_bar_count, 1u) == (unsigned)(NB - 1)) {
            g_bar_count = 0;
            __threadfence();
            g_bar_gen = gen + 1u;
        } else {
            while (g_bar_gen == gen) { }
        }
    }
    __syncthreads();
    __threadfence();   // acquire: flush stale L1
}

// ---------------- math helpers ----------------
__device__ __forceinline__ float sigf(float x) { return 1.0f / (1.0f + expf(-x)); }

__device__ __forceinline__ void ffma2(unsigned long long& acc,
                                      unsigned long long a,
                                      unsigned long long b) {
    asm("fma.rn.f32x2 %0, %1, %2, %0;" : "+l"(acc) : "l"(a), "l"(b));
}
__device__ __forceinline__ unsigned long long packf2(float lo, float hi) {
    unsigned long long r;
    asm("mov.b64 %0, {%1, %2};" : "=l"(r) : "f"(lo), "f"(hi));
    return r;
}
__device__ __forceinline__ float sumf2(unsigned long long v) {
    float lo = __uint_as_float((unsigned)(v & 0xffffffffu));
    float hi = __uint_as_float((unsigned)(v >> 32));
    return lo + hi;
}

// ---------------- LSTM layer phase ----------------
// CTA tile: 64 rows x 32 interleaved cols (8 u x 4 gates). Warp = 8 rows x 32 cols,
// so weight LDGs are one contiguous 128B line per k, A reads are warp-broadcast LDS.
__device__ __forceinline__ void layer_phase(
    const float* __restrict__ A0, int lda0, int Kin,
    const float* __restrict__ Hold,
    const float* __restrict__ Wr,       // reordered [(Kin+1024)][4096]
    const float* __restrict__ bias,     // original layout [4096]
    const float* __restrict__ Cold,
    float* __restrict__ Cnew, float* __restrict__ Hnew,
    float* As, float* zs, int cta, int tid)
{
    const int c32 = tid & 31;
    const int r0  = (tid >> 5) * 8;
    const int m   = cta * 32 + c32;          // interleaved column

    unsigned long long acc[8];
    #pragma unroll
    for (int i = 0; i < 8; i++) acc[i] = 0ull;

    #pragma unroll
    for (int seg = 0; seg < 2; seg++) {
        const float* A   = seg ? Hold : A0;
        const int    lda = seg ? U_DIM : lda0;
        const int    Ks  = seg ? U_DIM : Kin;
        const int    wr0 = seg ? Kin : 0;
        const int ntiles = Ks / KT;

        float4 st[8];
        // prologue: load tile 0 into regs
        #pragma unroll
        for (int q = 0; q < 8; q++) {
            int idx = tid + q * NT;
            int r = idx >> 5, kq = idx & 31;
            st[q] = *(const float4*)&A[(size_t)r * lda + kq * 4];
        }

        for (int j = 0; j < ntiles; j++) {
            __syncthreads();               // previous tile fully consumed
            #pragma unroll
            for (int q = 0; q < 8; q++) {
                int idx = tid + q * NT;
                int r = idx >> 5, kq = idx & 31;
                *(float4*)&As[r * KT + kq * 4] = st[q];
            }
            if (j + 1 < ntiles) {          // prefetch next tile (overlaps compute)
                int kb = (j + 1) * KT;
                #pragma unroll
                for (int q = 0; q < 8; q++) {
                    int idx = tid + q * NT;
                    int r = idx >> 5, kq = idx & 31;
                    st[q] = *(const float4*)&A[(size_t)r * lda + kb + kq * 4];
                }
            }
            __syncthreads();

            const float* Wp = Wr + (((size_t)(wr0 + j * KT)) << 12) + m;
            #pragma unroll 8
            for (int k4 = 0; k4 < KT; k4 += 4) {
                float w0 = Wp[(size_t)(k4 + 0) << 12];
                float w1 = Wp[(size_t)(k4 + 1) << 12];
                float w2 = Wp[(size_t)(k4 + 2) << 12];
                float w3 = Wp[(size_t)(k4 + 3) << 12];
                unsigned long long w01 = packf2(w0, w1);
                unsigned long long w23 = packf2(w2, w3);
                #pragma unroll
                for (int i = 0; i < 8; i++) {
                    ulonglong2 a2 = *(const ulonglong2*)&As[(r0 + i) * KT + k4];
                    ffma2(acc[i], a2.x, w01);
                    ffma2(acc[i], a2.y, w23);
                }
            }
        }
    }

    // z = acc + bias ; bias in original layout: n = g*1024 + u
    const float bv = bias[(c32 & 3) * 1024 + cta * 8 + (c32 >> 2)];
    __syncthreads();
    #pragma unroll
    for (int i = 0; i < 8; i++)
        zs[(r0 + i) * 32 + c32] = sumf2(acc[i]) + bv;
    __syncthreads();

    // fused gate update: 512 cells per CTA, 2 per thread
    const int u0 = cta * 8;
    #pragma unroll
    for (int pp = 0; pp < 2; pp++) {
        int pidx = tid + pp * NT;
        int row  = pidx >> 3;
        int uu   = pidx & 7;
        float4 zv = *(float4*)&zs[row * 32 + uu * 4];   // (i, j, f, o)
        int   ui = u0 + uu;
        float co = Cold[row * U_DIM + ui];
        float cn = co * sigf(zv.z + 1.0f) + sigf(zv.x) * tanhf(zv.y);
        float hn = sigf(zv.w) * tanhf(cn);
        Cnew[row * U_DIM + ui] = cn;
        Hnew[row * U_DIM + ui] = hn;
    }
}

// ---------------- fused dense + layernorm + relu + emit ----------------
// 64 CTAs each own one batch row; remaining CTAs idle to the barrier.
__device__ __forceinline__ void dense_ln_phase(
    const float* __restrict__ H2, const float* __restrict__ Wd,
    const float* __restrict__ bd,
    const float* __restrict__ gamma, const float* __restrict__ beta,
    float* __restrict__ out, float* h2s, float* red, int t, int cta, int tid)
{
    if (cta >= B_ROWS) return;
    const int row = cta;

    // stage h2 row (1024 floats) into smem
    *(float4*)&h2s[tid * 4] = *(const float4*)&H2[(size_t)row * U_DIM + tid * 4];
    __syncthreads();

    float acc = 0.0f;
    #pragma unroll 8
    for (int k = 0; k < U_DIM; k++)
        acc = fmaf(h2s[k], Wd[(size_t)k * F_DIM + tid], acc);
    float v = acc + bd[tid];

    red[tid] = v; __syncthreads();
    #pragma unroll
    for (int s = 128; s > 0; s >>= 1) {
        if (tid < s) red[tid] += red[tid + s];
        __syncthreads();
    }
    float mu = red[0] * (1.0f / 256.0f);
    __syncthreads();

    float d = v - mu;
    red[tid] = d * d; __syncthreads();
    #pragma unroll
    for (int s = 128; s > 0; s >>= 1) {
        if (tid < s) red[tid] += red[tid + s];
        __syncthreads();
    }
    float var = red[0] * (1.0f / 256.0f);

    float o = d * rsqrtf(var + 1e-12f) * gamma[tid] + beta[tid];
    o = fmaxf(o, 0.0f);
    g_emit[row * F_DIM + tid] = o;
    out[(size_t)row * T_STEPS * F_DIM + (size_t)t * F_DIM + tid] = o;
}

// ---------------- persistent kernel ----------------
__global__ void __launch_bounds__(NT, 1) lstm_persistent(
    const float* __restrict__ input, const unsigned char* __restrict__ condb,
    const float* __restrict__ b0, const float* __restrict__ b1,
    const float* __restrict__ b2,
    const float* __restrict__ Wd, const float* __restrict__ bd,
    const float* __restrict__ gamma, const float* __restrict__ beta,
    float* __restrict__ out)
{
    __shared__ __align__(16) float As[B_ROWS * KT];   // 32KB
    __shared__ __align__(16) float zs[B_ROWS * 32];   // 8KB
    __shared__ __align__(16) float h2s[U_DIM];        // 4KB
    __shared__ float red[NT];                         // 1KB

    const int cta = blockIdx.x, tid = threadIdx.x;

    const float* Wr0 = g_Wr;
    const float* Wr1 = g_Wr + (size_t)1280 * 4096;
    const float* Wr2 = g_Wr + (size_t)(1280 + 2048) * 4096;

    // --- detect dtype of conditioned_lst: bool-u8 vs int32 vs float32 ---
    int p1 = 0, p23 = 0;
    for (int i = tid; i < T_STEPS; i += NT) {
        unsigned char bv = condb[i];
        if (bv != 0) {
            if ((i & 3) == 1) p1 = 1;
            if ((i & 3) >= 2) p23 = 1;
        }
    }
    const int is_u8  = __syncthreads_or(p1);
    const int is_f32 = __syncthreads_or(p23) && !is_u8;
    const int*   cond32 = (const int*)condb;
    const float* condf  = (const float*)condb;

    // --- zero init ping-pong state ---
    {
        float* hflat = &g_h[0][0][0][0];
        float* cflat = &g_c[0][0][0][0];
        const int tot = 2 * 3 * B_ROWS * U_DIM;
        for (int i = cta * NT + tid; i < tot; i += NB * NT) {
            hflat[i] = 0.0f; cflat[i] = 0.0f;
        }
    }
    grid_barrier();

    for (int t = 0; t < T_STEPS; t++) {
        const int p = t & 1, q = p ^ 1;
        int cv;
        if (is_u8)       cv = (int)condb[t];
        else if (is_f32) cv = (condf[t] != 0.0f);
        else             cv = cond32[t];
        const bool  use_in = (t == 0) || (cv != 0);
        const float* x  = use_in ? (input + (size_t)t * F_DIM) : g_emit;
        const int   ldx = use_in ? (T_STEPS * F_DIM) : F_DIM;

        layer_phase(x, ldx, F_DIM, &g_h[q][0][0][0], Wr0, b0,
                    &g_c[q][0][0][0], &g_c[p][0][0][0], &g_h[p][0][0][0],
                    As, zs, cta, tid);
        grid_barrier();

        layer_phase(&g_h[p][0][0][0], U_DIM, U_DIM, &g_h[q][1][0][0], Wr1, b1,
                    &g_c[q][1][0][0], &g_c[p][1][0][0], &g_h[p][1][0][0],
                    As, zs, cta, tid);
        grid_barrier();

        layer_phase(&g_h[p][1][0][0], U_DIM, U_DIM, &g_h[q][2][0][0], Wr2, b2,
                    &g_c[q][2][0][0], &g_c[p][2][0][0], &g_h[p][2][0][0],
                    As, zs, cta, tid);
        grid_barrier();

        dense_ln_phase(&g_h[p][2][0][0], Wd, bd, gamma, beta, out,
                       h2s, red, t, cta, tid);
        grid_barrier();
    }
}

extern "C" void kernel_launch(void* const* d_in, const int* in_sizes, int n_in,
                              void* d_out, int out_size) {
    (void)in_sizes; (void)n_in; (void)out_size;

    float* Wr0 = nullptr, *Wr1 = nullptr, *Wr2 = nullptr;
    cudaGetSymbolAddress((void**)&Wr0, g_Wr);
    Wr1 = Wr0 + (size_t)1280 * 4096;
    Wr2 = Wr0 + (size_t)(1280 + 2048) * 4096;

    const int t0 = 1280 * 4096, t1 = 2048 * 4096;
    reorder_w<<<(t0 + 255) / 256, 256>>>((const float*)d_in[2], Wr0, t0);
    reorder_w<<<(t1 + 255) / 256, 256>>>((const float*)d_in[4], Wr1, t1);
    reorder_w<<<(t1 + 255) / 256, 256>>>((const float*)d_in[6], Wr2, t1);

    lstm_persistent<<<NB, NT>>>(
        (const float*)d_in[0], (const unsigned char*)d_in[1],
        (const float*)d_in[3],   // b0
        (const float*)d_in[5],   // b1
        (const float*)d_in[7],   // b2
        (const float*)d_in[8],   // Wd
        (const float*)d_in[9],   // bd
        (const float*)d_in[10],  // gamma
        (const float*)d_in[11],  // beta
        (float*)d_out);
}